// round 1
// baseline (speedup 1.0000x reference)
#include <cuda_runtime.h>
#include <cstdint>

#define N_NODES 10000
#define N_EDGES 640000
#define D 128

// Scratch for y = x @ W^T  (allocation-free: __device__ global)
__device__ float g_y[N_NODES * D];
__device__ int g_idx64;  // 1 if src/dst are int64, 0 if int32

// ---------------------------------------------------------------------------
// Sniff index dtype: if the first 64 int64-interpretations are all valid node
// ids, the buffer is int64. For int32 data the odds of that are ~(1e-4)^64.
// Deterministic given fixed input data.
// ---------------------------------------------------------------------------
__global__ void sniff_kernel(const void* __restrict__ srcp) {
    const long long* p = (const long long*)srcp;
    int is64 = 1;
    for (int i = 0; i < 64; i++) {
        long long v = p[i];
        if (v < 0 || v >= N_NODES) { is64 = 0; break; }
    }
    g_idx64 = is64;
}

// ---------------------------------------------------------------------------
// y[n][o] = sum_d x[n][d] * W[o][d]
// 128 threads/block (one output column each), 8 nodes per block.
// W rows stream through L1 (64KB, fully resident); x rows staged in shared.
// ---------------------------------------------------------------------------
__global__ void __launch_bounds__(128) gemm_xwt_kernel(
    const float* __restrict__ x, const float* __restrict__ W,
    float* __restrict__ y)
{
    const int NPB = 8;
    __shared__ float4 xs[NPB][32];

    int n0 = blockIdx.x * NPB;
    int o  = threadIdx.x;  // output column 0..127

    // Stage 8 x-rows (8 * 128 floats = 8 * 32 float4)
    for (int i = threadIdx.x; i < NPB * 32; i += 128) {
        int n = i >> 5, c = i & 31;
        int node = n0 + n;
        xs[n][c] = (node < N_NODES) ? ((const float4*)x)[node * 32 + c]
                                    : make_float4(0.f, 0.f, 0.f, 0.f);
    }
    __syncthreads();

    float acc[NPB];
#pragma unroll
    for (int n = 0; n < NPB; n++) acc[n] = 0.f;

    const float4* Wo = (const float4*)(W + o * D);
#pragma unroll 8
    for (int c = 0; c < 32; c++) {
        float4 w = __ldg(&Wo[c]);
#pragma unroll
        for (int n = 0; n < NPB; n++) {
            float4 xv = xs[n][c];  // broadcast across warp: conflict-free
            acc[n] += w.x * xv.x + w.y * xv.y + w.z * xv.z + w.w * xv.w;
        }
    }

#pragma unroll
    for (int n = 0; n < NPB; n++) {
        int node = n0 + n;
        if (node < N_NODES) y[node * D + o] = acc[n];
    }
}

// ---------------------------------------------------------------------------
// out[n][o] = b[o]   (bias init; scatter accumulates on top)
// ---------------------------------------------------------------------------
__global__ void init_out_kernel(const float* __restrict__ b,
                                float* __restrict__ out)
{
    int i = blockIdx.x * blockDim.x + threadIdx.x;
    if (i < N_NODES * D) out[i] = __ldg(&b[i & (D - 1)]);
}

// ---------------------------------------------------------------------------
// Edge scatter: one warp per edge.
//   out[dst] += v * y[src]   via red.global.add.v4.f32 (16B per lane)
// y and out are both L2-resident (5MB each).
// ---------------------------------------------------------------------------
__global__ void __launch_bounds__(256) scatter_kernel(
    const void* __restrict__ srcp, const void* __restrict__ dstp,
    const float* __restrict__ vals, const float* __restrict__ y,
    float* __restrict__ out)
{
    int t = blockIdx.x * blockDim.x + threadIdx.x;
    int e = t >> 5;
    int lane = t & 31;
    if (e >= N_EDGES) return;

    int s, d;
    if (g_idx64) {
        s = (int)((const long long*)srcp)[e];
        d = (int)((const long long*)dstp)[e];
    } else {
        s = ((const int*)srcp)[e];
        d = ((const int*)dstp)[e];
    }
    float v = __ldg(&vals[e]);

    float4 m = __ldg(&((const float4*)y)[s * 32 + lane]);
    m.x *= v; m.y *= v; m.z *= v; m.w *= v;

    float* p = out + (size_t)d * D + lane * 4;
    asm volatile("red.global.add.v4.f32 [%0], {%1, %2, %3, %4};"
                 :: "l"(p), "f"(m.x), "f"(m.y), "f"(m.z), "f"(m.w)
                 : "memory");
}

// ---------------------------------------------------------------------------
// Launch
// Inputs (metadata order = setup_inputs dict order):
//   0: x        [10000,128] f32
//   1: src      [640000]    int64 (or int32 if jax x64 disabled -> sniffed)
//   2: dst      [640000]    int64/int32
//   3: adj_vals [640000]    f32
//   4: W        [128,128]   f32
//   5: b        [128]       f32
// Output: [10000,128] f32
// ---------------------------------------------------------------------------
extern "C" void kernel_launch(void* const* d_in, const int* in_sizes, int n_in,
                              void* d_out, int out_size)
{
    const float* x    = (const float*)d_in[0];
    const void*  srcp = d_in[1];
    const void*  dstp = d_in[2];
    const float* vals = (const float*)d_in[3];
    const float* W    = (const float*)d_in[4];
    const float* b    = (const float*)d_in[5];
    float* out = (float*)d_out;

    float* y = nullptr;
    cudaGetSymbolAddress((void**)&y, g_y);

    sniff_kernel<<<1, 1>>>(srcp);

    gemm_xwt_kernel<<<(N_NODES + 7) / 8, 128>>>(x, W, y);

    init_out_kernel<<<(N_NODES * D + 255) / 256, 256>>>(b, out);

    const long long threads = (long long)N_EDGES * 32;
    scatter_kernel<<<(unsigned)((threads + 255) / 256), 256>>>(
        srcp, dstp, vals, y, out);
}

// round 2
// speedup vs baseline: 1.0247x; 1.0247x over previous
#include <cuda_runtime.h>
#include <cuda_fp16.h>
#include <cstdint>

#define N_NODES 10000
#define N_EDGES 640000
#define D 128

// ---- allocation-free scratch (__device__ globals) -------------------------
__device__ __half g_yh[N_NODES * D];     // y = x @ W^T in fp16 (2.5MB, L2-resident)
__device__ int    g_count[N_NODES];      // per-dst edge counts
__device__ int    g_cursor[N_NODES];     // excl prefix -> (after fill) incl prefix
__device__ int    g_esrc[N_EDGES];       // src permuted by dst
__device__ float  g_eval[N_EDGES];       // val permuted by dst
__device__ int    g_idx64;               // 1 if indices are int64

// ---------------------------------------------------------------------------
// Sniff index dtype (one warp, parallel loads + ballot). If the first 32
// int64-interpretations are all valid node ids, it's int64 (false positive
// odds for int32 data ~ (1e-4)^32).
// ---------------------------------------------------------------------------
__global__ void sniff_kernel(const void* __restrict__ srcp) {
    const long long* p = (const long long*)srcp;
    long long v = p[threadIdx.x];
    int ok = (v >= 0 && v < N_NODES);
    int all = __all_sync(0xFFFFFFFFu, ok);
    if (threadIdx.x == 0) g_idx64 = all;
}

__device__ __forceinline__ int load_idx(const void* p, int e) {
    if (g_idx64) return (int)((const long long*)p)[e];
    return ((const int*)p)[e];
}

// ---------------------------------------------------------------------------
// Histogram of dst (g_count pre-zeroed via cudaMemsetAsync)
// ---------------------------------------------------------------------------
__global__ void __launch_bounds__(256) hist_kernel(const void* __restrict__ dstp) {
    int e = blockIdx.x * blockDim.x + threadIdx.x;
    if (e >= N_EDGES) return;
    int d = load_idx(dstp, e);
    asm volatile("red.global.add.s32 [%0], %1;" :: "l"(g_count + d), "r"(1) : "memory");
}

// ---------------------------------------------------------------------------
// Exclusive prefix sum over g_count -> g_cursor (single block, 1024 threads)
// ---------------------------------------------------------------------------
__global__ void __launch_bounds__(1024) scan_kernel() {
    __shared__ int sh[1024];
    __shared__ int carry_s;
    int t = threadIdx.x;
    if (t == 0) carry_s = 0;
    __syncthreads();
    for (int base = 0; base < N_NODES; base += 1024) {
        int idx = base + t;
        int v = (idx < N_NODES) ? g_count[idx] : 0;
        sh[t] = v;
        __syncthreads();
#pragma unroll
        for (int off = 1; off < 1024; off <<= 1) {
            int add = (t >= off) ? sh[t - off] : 0;
            __syncthreads();
            sh[t] += add;
            __syncthreads();
        }
        int carry = carry_s;
        if (idx < N_NODES) g_cursor[idx] = carry + sh[t] - v;  // exclusive
        __syncthreads();
        if (t == 1023) carry_s = carry + sh[1023];
        __syncthreads();
    }
}

// ---------------------------------------------------------------------------
// Fill CSR payload: pos = cursor[dst]++ ; esrc[pos]=src ; eval[pos]=val
// After this kernel, g_cursor[n] == inclusive prefix == end offset of node n.
// ---------------------------------------------------------------------------
__global__ void __launch_bounds__(256) fill_kernel(
    const void* __restrict__ srcp, const void* __restrict__ dstp,
    const float* __restrict__ vals)
{
    int e = blockIdx.x * blockDim.x + threadIdx.x;
    if (e >= N_EDGES) return;
    int d = load_idx(dstp, e);
    int s = load_idx(srcp, e);
    float v = __ldg(&vals[e]);
    int pos = atomicAdd(g_cursor + d, 1);
    g_esrc[pos] = s;
    g_eval[pos] = v;
}

// ---------------------------------------------------------------------------
// y[n][o] = sum_d x[n][d] * W[o][d], stored as fp16.
// 128 threads/block (one output column each), 8 nodes per block.
// ---------------------------------------------------------------------------
__global__ void __launch_bounds__(128) gemm_xwt_kernel(
    const float* __restrict__ x, const float* __restrict__ W)
{
    const int NPB = 8;
    __shared__ float4 xs[NPB][32];

    int n0 = blockIdx.x * NPB;
    int o  = threadIdx.x;

    for (int i = threadIdx.x; i < NPB * 32; i += 128) {
        int n = i >> 5, c = i & 31;
        int node = n0 + n;
        xs[n][c] = (node < N_NODES) ? ((const float4*)x)[node * 32 + c]
                                    : make_float4(0.f, 0.f, 0.f, 0.f);
    }
    __syncthreads();

    float acc[NPB];
#pragma unroll
    for (int n = 0; n < NPB; n++) acc[n] = 0.f;

    const float4* Wo = (const float4*)(W + o * D);
#pragma unroll 8
    for (int c = 0; c < 32; c++) {
        float4 w = __ldg(&Wo[c]);
#pragma unroll
        for (int n = 0; n < NPB; n++) {
            float4 xv = xs[n][c];
            acc[n] += w.x * xv.x + w.y * xv.y + w.z * xv.z + w.w * xv.w;
        }
    }

#pragma unroll
    for (int n = 0; n < NPB; n++) {
        int node = n0 + n;
        if (node < N_NODES) g_yh[node * D + o] = __float2half(acc[n]);
    }
}

// ---------------------------------------------------------------------------
// Aggregate: one warp per node.
//   out[n] = b + sum_{i in csr[n]} eval[i] * y[esrc[i]]
// Lane L owns columns [4L, 4L+4): reads 4 halves (8B LDG.64) per edge,
// accumulates fp32, writes one STG.128. No atomics anywhere.
// ---------------------------------------------------------------------------
__global__ void __launch_bounds__(256) aggregate_kernel(
    const float* __restrict__ b, float* __restrict__ out)
{
    int warp = (blockIdx.x * blockDim.x + threadIdx.x) >> 5;
    int lane = threadIdx.x & 31;
    if (warp >= N_NODES) return;
    int n = warp;

    int start = (n == 0) ? 0 : __ldg(g_cursor + n - 1);
    int end   = __ldg(g_cursor + n);

    const uint2* yv = (const uint2*)g_yh;  // 8B = 4 halves per lane

    float4 acc0 = make_float4(0.f, 0.f, 0.f, 0.f);
    float4 acc1 = make_float4(0.f, 0.f, 0.f, 0.f);

    int i = start;
    for (; i + 1 < end; i += 2) {
        int   s0 = __ldg(g_esrc + i);
        float v0 = __ldg(g_eval + i);
        int   s1 = __ldg(g_esrc + i + 1);
        float v1 = __ldg(g_eval + i + 1);

        uint2 r0 = __ldg(&yv[s0 * 32 + lane]);
        uint2 r1 = __ldg(&yv[s1 * 32 + lane]);

        float2 a0 = __half22float2(*(const __half2*)&r0.x);
        float2 b0 = __half22float2(*(const __half2*)&r0.y);
        acc0.x += v0 * a0.x; acc0.y += v0 * a0.y;
        acc0.z += v0 * b0.x; acc0.w += v0 * b0.y;

        float2 a1 = __half22float2(*(const __half2*)&r1.x);
        float2 b1 = __half22float2(*(const __half2*)&r1.y);
        acc1.x += v1 * a1.x; acc1.y += v1 * a1.y;
        acc1.z += v1 * b1.x; acc1.w += v1 * b1.y;
    }
    if (i < end) {
        int   s0 = __ldg(g_esrc + i);
        float v0 = __ldg(g_eval + i);
        uint2 r0 = __ldg(&yv[s0 * 32 + lane]);
        float2 a0 = __half22float2(*(const __half2*)&r0.x);
        float2 b0 = __half22float2(*(const __half2*)&r0.y);
        acc0.x += v0 * a0.x; acc0.y += v0 * a0.y;
        acc0.z += v0 * b0.x; acc0.w += v0 * b0.y;
    }

    float4 bias = __ldg(&((const float4*)b)[lane]);
    float4 r;
    r.x = acc0.x + acc1.x + bias.x;
    r.y = acc0.y + acc1.y + bias.y;
    r.z = acc0.z + acc1.z + bias.z;
    r.w = acc0.w + acc1.w + bias.w;
    ((float4*)out)[n * 32 + lane] = r;
}

// ---------------------------------------------------------------------------
// Launch
// ---------------------------------------------------------------------------
extern "C" void kernel_launch(void* const* d_in, const int* in_sizes, int n_in,
                              void* d_out, int out_size)
{
    const float* x    = (const float*)d_in[0];
    const void*  srcp = d_in[1];
    const void*  dstp = d_in[2];
    const float* vals = (const float*)d_in[3];
    const float* W    = (const float*)d_in[4];
    const float* b    = (const float*)d_in[5];
    float* out = (float*)d_out;

    void* count_ptr = nullptr;
    cudaGetSymbolAddress(&count_ptr, g_count);

    sniff_kernel<<<1, 32>>>(srcp);
    cudaMemsetAsync(count_ptr, 0, N_NODES * sizeof(int));

    hist_kernel<<<(N_EDGES + 255) / 256, 256>>>(dstp);
    gemm_xwt_kernel<<<(N_NODES + 7) / 8, 128>>>(x, W);
    scan_kernel<<<1, 1024>>>();
    fill_kernel<<<(N_EDGES + 255) / 256, 256>>>(srcp, dstp, vals);

    aggregate_kernel<<<(N_NODES * 32 + 255) / 256, 256>>>(b, out);
}